// round 1
// baseline (speedup 1.0000x reference)
#include <cuda_runtime.h>
#include <math.h>

// Problem constants
#define BB   256
#define NN   32
#define PPL  32
#define DIN  128
#define DF1  64
#define DF2  32

// out layout: value [B,32,32,32] | weight [B,32,32] | wp [B,32,32]
#define VAL_ELEMS (8388608ull)            // 256*32*32*32
#define WOFF      (8388608ull)
#define WPOFF     (8650752ull)            // WOFF + 256*1024

// Scratch (device globals: no allocation)
__device__ float g_M [DIN * DIN];
__device__ float g_Mp[DIN * DIN];
__device__ float g_U [BB * NN * DF1];     // 2M floats
__device__ float g_V [BB * NN * DF1];

__device__ __forceinline__ float warp_max(float v) {
    #pragma unroll
    for (int o = 16; o; o >>= 1) v = fmaxf(v, __shfl_xor_sync(0xffffffffu, v, o));
    return v;
}
__device__ __forceinline__ float warp_sum(float v) {
    #pragma unroll
    for (int o = 16; o; o >>= 1) v += __shfl_xor_sync(0xffffffffu, v, o);
    return v;
}

// ---------------------------------------------------------------------------
// Kernel 0: M = W_q @ W_k^T, Mp = W_qp @ W_kp^T   (128x128 each)
// grid (16,2) x 256 threads. Block computes 8 rows of one M.
// ---------------------------------------------------------------------------
__global__ void k0_precompute(const float* __restrict__ Wq, const float* __restrict__ Wk,
                              const float* __restrict__ Wqp, const float* __restrict__ Wkp) {
    __shared__ float sA[8 * 128];
    __shared__ float sB[32 * 129];
    const float* A  = blockIdx.y ? Wqp : Wq;
    const float* Bm = blockIdx.y ? Wkp : Wk;
    float* out      = blockIdx.y ? g_Mp : g_M;
    const int e0 = blockIdx.x * 8;
    const int t  = threadIdx.x;
    for (int idx = t; idx < 8 * 128; idx += 256) sA[idx] = A[e0 * 128 + idx];
    const int w = t >> 5, l = t & 31;
    for (int ft = 0; ft < 4; ++ft) {
        __syncthreads();
        for (int idx = t; idx < 32 * 128; idx += 256) {
            int ff = idx >> 7, d = idx & 127;
            sB[ff * 129 + d] = Bm[(ft * 32 + ff) * 128 + d];
        }
        __syncthreads();
        float acc = 0.f;
        #pragma unroll 4
        for (int d = 0; d < 128; ++d)
            acc = fmaf(sA[w * 128 + d], sB[l * 129 + d], acc);
        out[(e0 + w) * 128 + ft * 32 + l] = acc;
    }
}

// ---------------------------------------------------------------------------
// GEMM helper: Y[32,OUT] = act( X[32,128] @ W[128,OUT] )   (8 warps, 256 thr)
// Warp w handles rows 4w..4w+3. OUT=128: lane -> float4 cols; OUT=64: float2.
// USEPOL: for columns e>=96, operand comes from POL[i][e-96] (the "op" input).
// ---------------------------------------------------------------------------
template <int OUT, bool TANH, bool USEPOL>
__device__ __forceinline__ void gemm32(const float* __restrict__ X, int xstr,
                                       const float* __restrict__ POL,
                                       const float* __restrict__ W,
                                       float* __restrict__ Y) {
    const int w  = threadIdx.x >> 5;
    const int l  = threadIdx.x & 31;
    const int r0 = w * 4;
    if constexpr (OUT == 128) {
        float4 a0 = {0,0,0,0}, a1 = a0, a2 = a0, a3 = a0;
        const float4* W4 = reinterpret_cast<const float4*>(W);
        #pragma unroll 4
        for (int e = 0; e < 128; ++e) {
            float4 wv = W4[e * 32 + l];
            float x0, x1, x2, x3;
            if (USEPOL && e >= 96) {
                x0 = POL[(r0 + 0) * 32 + (e - 96)];
                x1 = POL[(r0 + 1) * 32 + (e - 96)];
                x2 = POL[(r0 + 2) * 32 + (e - 96)];
                x3 = POL[(r0 + 3) * 32 + (e - 96)];
            } else {
                x0 = X[(r0 + 0) * xstr + e];
                x1 = X[(r0 + 1) * xstr + e];
                x2 = X[(r0 + 2) * xstr + e];
                x3 = X[(r0 + 3) * xstr + e];
            }
            a0.x = fmaf(x0, wv.x, a0.x); a0.y = fmaf(x0, wv.y, a0.y);
            a0.z = fmaf(x0, wv.z, a0.z); a0.w = fmaf(x0, wv.w, a0.w);
            a1.x = fmaf(x1, wv.x, a1.x); a1.y = fmaf(x1, wv.y, a1.y);
            a1.z = fmaf(x1, wv.z, a1.z); a1.w = fmaf(x1, wv.w, a1.w);
            a2.x = fmaf(x2, wv.x, a2.x); a2.y = fmaf(x2, wv.y, a2.y);
            a2.z = fmaf(x2, wv.z, a2.z); a2.w = fmaf(x2, wv.w, a2.w);
            a3.x = fmaf(x3, wv.x, a3.x); a3.y = fmaf(x3, wv.y, a3.y);
            a3.z = fmaf(x3, wv.z, a3.z); a3.w = fmaf(x3, wv.w, a3.w);
        }
        float4 accs[4] = {a0, a1, a2, a3};
        #pragma unroll
        for (int r = 0; r < 4; ++r) {
            float4 v = accs[r];
            if (TANH) { v.x = tanhf(v.x); v.y = tanhf(v.y); v.z = tanhf(v.z); v.w = tanhf(v.w); }
            *reinterpret_cast<float4*>(&Y[(r0 + r) * 128 + 4 * l]) = v;
        }
    } else {  // OUT == 64
        float2 a0 = {0,0}, a1 = a0, a2 = a0, a3 = a0;
        const float2* W2 = reinterpret_cast<const float2*>(W);
        #pragma unroll 4
        for (int e = 0; e < 128; ++e) {
            float2 wv = W2[e * 32 + l];
            float x0 = X[(r0 + 0) * xstr + e];
            float x1 = X[(r0 + 1) * xstr + e];
            float x2 = X[(r0 + 2) * xstr + e];
            float x3 = X[(r0 + 3) * xstr + e];
            a0.x = fmaf(x0, wv.x, a0.x); a0.y = fmaf(x0, wv.y, a0.y);
            a1.x = fmaf(x1, wv.x, a1.x); a1.y = fmaf(x1, wv.y, a1.y);
            a2.x = fmaf(x2, wv.x, a2.x); a2.y = fmaf(x2, wv.y, a2.y);
            a3.x = fmaf(x3, wv.x, a3.x); a3.y = fmaf(x3, wv.y, a3.y);
        }
        float2 accs[4] = {a0, a1, a2, a3};
        #pragma unroll
        for (int r = 0; r < 4; ++r)
            *reinterpret_cast<float2*>(&Y[(r0 + r) * 64 + 2 * l]) = accs[r];
    }
}

// ---------------------------------------------------------------------------
// Kernel 1: per-batch block. Computes weight, wp (to d_out) and U, V (scratch).
// ---------------------------------------------------------------------------
#define SM1_FLOATS 28096
#define SM1_BYTES  (SM1_FLOATS * 4)
#define SOFTMAX_SCALE 0.08838834764831843f   // 1/sqrt(128)

extern "C" __global__ void __launch_bounds__(256, 2)
k1_batch(const float* __restrict__ states, const float* __restrict__ policies,
         const float* __restrict__ actions, const float* __restrict__ states_people,
         const float* __restrict__ actions_people,
         const float* __restrict__ Wv, const float* __restrict__ Wvp,
         const float* __restrict__ Wf1, float* __restrict__ out) {
    extern __shared__ float sm[];
    float* s_oa  = sm;                 // 32 x 133  (stride 133: conflict-free column reads)
    float* s_oap = s_oa  + 4256;       // 32 x 133
    float* s_pol = s_oap + 4256;       // 32 x 32
    float* s_t   = s_pol + 1024;       // 32 x 128
    float* s_tp  = s_t   + 4096;       // 32 x 128
    float* s_sc  = s_tp  + 4096;       // 32 x 33
    float* s_sp  = s_sc  + 1056;       // 32 x 33
    float* s_w   = s_sp  + 1056;       // 32 x 33   weight[a][j]
    float* s_wp  = s_w   + 1056;       // 32 x 33   wp[n][p]
    float* s_A1  = s_wp  + 1056;       // 32 x 64
    float* s_B1  = s_A1  + 2048;       // 32 x 64
    float* s_C1  = s_B1  + 2048;       // 32 x 64

    const int b = blockIdx.x;
    const int t = threadIdx.x;

    // --- load inputs: oa = [states|actions], oap = [states_p|actions_p], pol ---
    {
        const float* st  = states         + (size_t)b * 32 * 96;
        const float* ac  = actions        + (size_t)b * 1024;
        const float* stp = states_people  + (size_t)b * 32 * 96;
        const float* acp = actions_people + (size_t)b * 1024;
        const float* po  = policies       + (size_t)b * 1024;
        for (int idx = t; idx < 4096; idx += 256) {
            int i = idx >> 7, c = idx & 127;
            s_oa [i * 133 + c] = (c < 96) ? st [i * 96 + c] : ac [i * 32 + c - 96];
            s_oap[i * 133 + c] = (c < 96) ? stp[i * 96 + c] : acp[i * 32 + c - 96];
        }
        for (int idx = t; idx < 1024; idx += 256) s_pol[idx] = po[idx];
    }
    __syncthreads();

    // --- t = oa @ M ; tp = oa @ Mp  (rows are warp-private thereafter) ---
    gemm32<128, false, false>(s_oa, 133, nullptr, g_M,  s_t);
    gemm32<128, false, false>(s_oa, 133, nullptr, g_Mp, s_tp);

    // --- scores[i,j] = t[i]·oa[j] ; sp[n,p] = tp[n]·oap[p] ---
    {
        const int w = t >> 5, l = t & 31, r0 = 4 * w;
        float a0 = 0, a1 = 0, a2 = 0, a3 = 0;
        float c0 = 0, c1 = 0, c2 = 0, c3 = 0;
        #pragma unroll 4
        for (int f = 0; f < 128; ++f) {
            float oj = s_oa [l * 133 + f];
            float pj = s_oap[l * 133 + f];
            a0 = fmaf(s_t [(r0 + 0) * 128 + f], oj, a0);
            a1 = fmaf(s_t [(r0 + 1) * 128 + f], oj, a1);
            a2 = fmaf(s_t [(r0 + 2) * 128 + f], oj, a2);
            a3 = fmaf(s_t [(r0 + 3) * 128 + f], oj, a3);
            c0 = fmaf(s_tp[(r0 + 0) * 128 + f], pj, c0);
            c1 = fmaf(s_tp[(r0 + 1) * 128 + f], pj, c1);
            c2 = fmaf(s_tp[(r0 + 2) * 128 + f], pj, c2);
            c3 = fmaf(s_tp[(r0 + 3) * 128 + f], pj, c3);
        }
        s_sc[(r0 + 0) * 33 + l] = a0;  s_sc[(r0 + 1) * 33 + l] = a1;
        s_sc[(r0 + 2) * 33 + l] = a2;  s_sc[(r0 + 3) * 33 + l] = a3;
        s_sp[(r0 + 0) * 33 + l] = c0;  s_sp[(r0 + 1) * 33 + l] = c1;
        s_sp[(r0 + 2) * 33 + l] = c2;  s_sp[(r0 + 3) * 33 + l] = c3;
    }
    __syncthreads();

    // --- column softmaxes: weight[a,j] = smax_j sc[j,a]; wp[n,p] = smax_n sp[n,p] ---
    {
        const int w = t >> 5, l = t & 31;
        #pragma unroll
        for (int k = 0; k < 4; ++k) {
            int a = w + 8 * k;
            // weight (lane = j)
            float v  = s_sc[l * 33 + a] * SOFTMAX_SCALE;
            float m  = warp_max(v);
            float e  = expf(v - m);
            float s  = warp_sum(e);
            float wg = e / s;
            s_w[a * 33 + l] = wg;
            out[WOFF + ((size_t)b * 32 + a) * 32 + l] = wg;   // coalesced over j
            // wp (column p = a, lane = n)
            float v2  = s_sp[l * 33 + a] * SOFTMAX_SCALE;
            float m2  = warp_max(v2);
            float e2  = expf(v2 - m2);
            float s2  = warp_sum(e2);
            s_wp[l * 33 + a] = e2 / s2;
        }
    }

    // --- va,A1 ; vp,B1 ; avp,C1  (warp-private row chains; reuse s_t/s_tp) ---
    gemm32<128, true,  false>(s_oa,  133, nullptr, Wv,            s_t);   // va
    gemm32<64,  false, false>(s_t,   128, nullptr, Wf1,           s_A1);  // va @ W1_top
    gemm32<128, true,  true >(s_oa,  133, s_pol,   Wv,            s_tp);  // vp (op = oa w/ policies)
    gemm32<64,  false, false>(s_tp,  128, nullptr, Wf1,           s_B1);  // vp @ W1_top
    gemm32<128, true,  false>(s_oap, 133, nullptr, Wvp,           s_t);   // avp
    gemm32<64,  false, false>(s_t,   128, nullptr, Wf1 + 128*64,  s_C1);  // avp @ W1_bot
    __syncthreads();

    // --- wp to global (coalesced) ---
    for (int idx = t; idx < 1024; idx += 256) {
        int n = idx >> 5, p = idx & 31;
        out[WPOFF + (size_t)b * 1024 + idx] = s_wp[n * 33 + p];
    }

    // --- U[a,f] = (w[a,:]·A1[:,f] + wp[a,:]·C1[:,f])/32 ; V = (B1-A1)/32 ---
    for (int idx = t; idx < 2048; idx += 256) {
        int a = idx >> 6, f = idx & 63;
        float acc = 0.f;
        #pragma unroll
        for (int j = 0; j < 32; ++j) acc = fmaf(s_w [a * 33 + j], s_A1[j * 64 + f], acc);
        #pragma unroll
        for (int p = 0; p < 32; ++p) acc = fmaf(s_wp[a * 33 + p], s_C1[p * 64 + f], acc);
        g_U[(size_t)b * 2048 + idx] = acc * 0.03125f;
        g_V[(size_t)b * 2048 + idx] = (s_B1[idx] - s_A1[idx]) * 0.03125f;
    }
}

// ---------------------------------------------------------------------------
// Kernel 2: value[b,a,i,:] = lrelu(U[b,a] + weight[b,a,i]*V[b,i]) @ W_f2
// grid 1024 (b,quarter) x 256 threads; warp = a (8 per block), lane = i.
// ---------------------------------------------------------------------------
extern "C" __global__ void __launch_bounds__(256)
k2_value(const float* __restrict__ Wf2, float* __restrict__ out) {
    __shared__ float sU [8 * 64];
    __shared__ float sV [32 * 65];
    __shared__ float sW2[64 * 32];
    __shared__ float sW [8 * 33];
    const int t  = threadIdx.x;
    const int b  = blockIdx.x >> 2;
    const int a0 = (blockIdx.x & 3) * 8;

    for (int idx = t; idx < 2048; idx += 256) {
        int i = idx >> 6, f = idx & 63;
        sV[i * 65 + f] = g_V[(size_t)b * 2048 + idx];
    }
    for (int idx = t; idx < 512; idx += 256)
        sU[idx] = g_U[(size_t)b * 2048 + a0 * 64 + idx];
    for (int idx = t; idx < 2048; idx += 256) sW2[idx] = Wf2[idx];
    {
        int a = t >> 5, i = t & 31;
        sW[a * 33 + i] = out[WOFF + ((size_t)b * 32 + a0 + a) * 32 + i];
    }
    __syncthreads();

    const int w = t >> 5, l = t & 31;
    const float wai = sW[w * 33 + l];
    const float* Ua = &sU[w * 64];
    float4 acc[8];
    #pragma unroll
    for (int q = 0; q < 8; ++q) acc[q] = make_float4(0.f, 0.f, 0.f, 0.f);

    #pragma unroll 8
    for (int f = 0; f < 64; ++f) {
        float h = fmaf(wai, sV[l * 65 + f], Ua[f]);
        h = fmaxf(h, 0.f) + 0.01f * fminf(h, 0.f);       // leaky_relu(0.01)
        const float4* r2 = reinterpret_cast<const float4*>(&sW2[f * 32]);
        #pragma unroll
        for (int q = 0; q < 8; ++q) {
            float4 wv = r2[q];
            acc[q].x = fmaf(h, wv.x, acc[q].x);
            acc[q].y = fmaf(h, wv.y, acc[q].y);
            acc[q].z = fmaf(h, wv.z, acc[q].z);
            acc[q].w = fmaf(h, wv.w, acc[q].w);
        }
    }
    float4* op = reinterpret_cast<float4*>(out + (((size_t)b * 32 + a0 + w) * 32 + l) * 32);
    #pragma unroll
    for (int q = 0; q < 8; ++q) op[q] = acc[q];
}

// ---------------------------------------------------------------------------
extern "C" void kernel_launch(void* const* d_in, const int* in_sizes, int n_in,
                              void* d_out, int out_size) {
    const float* states         = (const float*)d_in[0];
    const float* policies       = (const float*)d_in[1];
    const float* actions        = (const float*)d_in[2];
    const float* states_people  = (const float*)d_in[3];
    const float* actions_people = (const float*)d_in[4];
    const float* Wk  = (const float*)d_in[5];
    const float* Wq  = (const float*)d_in[6];
    const float* Wv  = (const float*)d_in[7];
    const float* Wkp = (const float*)d_in[8];
    const float* Wqp = (const float*)d_in[9];
    const float* Wvp = (const float*)d_in[10];
    const float* Wf1 = (const float*)d_in[11];
    const float* Wf2 = (const float*)d_in[12];
    float* out = (float*)d_out;

    k0_precompute<<<dim3(16, 2), 256>>>(Wq, Wk, Wqp, Wkp);

    cudaFuncSetAttribute(k1_batch, cudaFuncAttributeMaxDynamicSharedMemorySize, SM1_BYTES);
    k1_batch<<<256, 256, SM1_BYTES>>>(states, policies, actions,
                                      states_people, actions_people,
                                      Wv, Wvp, Wf1, out);

    k2_value<<<1024, 256>>>(Wf2, out);
}

// round 2
// speedup vs baseline: 1.1709x; 1.1709x over previous
#include <cuda_runtime.h>
#include <math.h>

// Problem constants
#define BB   256
#define NN   32
#define DIN  128
#define DF1  64
#define DF2  32

// out layout: value [B,32,32,32] | weight [B,32,32] | wp [B,32,32]
#define WOFF      (8388608ull)
#define WPOFF     (8650752ull)

typedef unsigned long long ull;

// Scratch (device globals: no allocation)
__device__ float g_M [DIN * DIN];
__device__ float g_Mp[DIN * DIN];
__device__ float g_U [BB * NN * DF1];
__device__ float g_V [BB * NN * DF1];

// ---- packed f32x2 helpers (Blackwell FFMA2 path; ptxas never emits this) ----
__device__ __forceinline__ ull pk2(float v) {
    ull r; asm("mov.b64 %0, {%1, %1};" : "=l"(r) : "f"(v)); return r;
}
__device__ __forceinline__ ull ffma2(ull a, ull b, ull c) {
    ull d; asm("fma.rn.f32x2 %0, %1, %2, %3;" : "=l"(d) : "l"(a), "l"(b), "l"(c)); return d;
}
__device__ __forceinline__ float2 upk2(ull v) {
    float2 f; asm("mov.b64 {%0, %1}, %2;" : "=f"(f.x), "=f"(f.y) : "l"(v)); return f;
}

__device__ __forceinline__ float warp_max(float v) {
    #pragma unroll
    for (int o = 16; o; o >>= 1) v = fmaxf(v, __shfl_xor_sync(0xffffffffu, v, o));
    return v;
}
__device__ __forceinline__ float warp_sum(float v) {
    #pragma unroll
    for (int o = 16; o; o >>= 1) v += __shfl_xor_sync(0xffffffffu, v, o);
    return v;
}

// ---------------------------------------------------------------------------
// Kernel 0: M = W_q @ W_k^T, Mp = W_qp @ W_kp^T   (128x128 each)
// grid (16,2,2) = 64 blocks; block = 8 rows x 64 cols; 2 accumulators/thread.
// ---------------------------------------------------------------------------
__global__ void k0_precompute(const float* __restrict__ Wq, const float* __restrict__ Wk,
                              const float* __restrict__ Wqp, const float* __restrict__ Wkp) {
    __shared__ float sA[8 * 128];
    __shared__ float sB[64 * 129];
    const float* A  = blockIdx.z ? Wqp : Wq;
    const float* Bm = blockIdx.z ? Wkp : Wk;
    float* out      = blockIdx.z ? g_Mp : g_M;
    const int e0 = blockIdx.x * 8;
    const int c0 = blockIdx.y * 64;
    const int t  = threadIdx.x;
    for (int idx = t; idx < 1024; idx += 256) sA[idx] = A[e0 * 128 + idx];
    for (int idx = t; idx < 64 * 128; idx += 256) {
        int r = idx >> 7, d = idx & 127;
        sB[r * 129 + d] = Bm[(c0 + r) * 128 + d];
    }
    __syncthreads();
    const int w = t >> 5, l = t & 31;
    float a0 = 0.f, a1 = 0.f;
    #pragma unroll 8
    for (int d = 0; d < 128; ++d) {
        float av = sA[w * 128 + d];
        a0 = fmaf(av, sB[l * 129 + d], a0);
        a1 = fmaf(av, sB[(l + 32) * 129 + d], a1);
    }
    out[(e0 + w) * 128 + c0 + l]      = a0;
    out[(e0 + w) * 128 + c0 + 32 + l] = a1;
}

// ---------------------------------------------------------------------------
// Packed GEMM building blocks. Warp w owns rows r0=4w..4w+3 of the 32-row tile.
// mm_acc128: acc[4 rows][2 x f32x2] += X[rows,K] @ W[K,128] (thread = 4 cols 4l..4l+3)
// mm64:      Y[rows, 64] = X[rows,K] @ W[K,64]              (thread = 2 cols 2l..2l+1)
// ---------------------------------------------------------------------------
template <int K>
__device__ __forceinline__ void mm_acc128(const float* __restrict__ X, int xstr,
                                          const float* __restrict__ W,
                                          ull acc[4][2], int r0, int l) {
    const ulonglong2* W4 = reinterpret_cast<const ulonglong2*>(W);
    #pragma unroll 4
    for (int e = 0; e < K; ++e) {
        ulonglong2 wv = W4[e * 32 + l];
        #pragma unroll
        for (int r = 0; r < 4; ++r) {
            ull xx = pk2(X[(r0 + r) * xstr + e]);
            acc[r][0] = ffma2(xx, wv.x, acc[r][0]);
            acc[r][1] = ffma2(xx, wv.y, acc[r][1]);
        }
    }
}

__device__ __forceinline__ void store128(float* __restrict__ Y, ull acc[4][2],
                                         int r0, int l, bool do_tanh) {
    #pragma unroll
    for (int r = 0; r < 4; ++r) {
        float2 p0 = upk2(acc[r][0]);
        float2 p1 = upk2(acc[r][1]);
        float4 v = make_float4(p0.x, p0.y, p1.x, p1.y);
        if (do_tanh) { v.x = tanhf(v.x); v.y = tanhf(v.y); v.z = tanhf(v.z); v.w = tanhf(v.w); }
        *reinterpret_cast<float4*>(&Y[(r0 + r) * 128 + 4 * l]) = v;
    }
}

template <int K>
__device__ __forceinline__ void mm64(const float* __restrict__ X, int xstr,
                                     const float* __restrict__ W,
                                     float* __restrict__ Y, int r0, int l) {
    const ull* Wu = reinterpret_cast<const ull*>(W);
    ull acc[4] = {0, 0, 0, 0};
    #pragma unroll 4
    for (int e = 0; e < K; ++e) {
        ull wv = Wu[e * 32 + l];
        #pragma unroll
        for (int r = 0; r < 4; ++r)
            acc[r] = ffma2(pk2(X[(r0 + r) * xstr + e]), wv, acc[r]);
    }
    #pragma unroll
    for (int r = 0; r < 4; ++r) {
        float2 p = upk2(acc[r]);
        *reinterpret_cast<float2*>(&Y[(r0 + r) * 64 + 2 * l]) = p;
    }
}

// ---------------------------------------------------------------------------
// Kernel 1: per-batch block. Computes weight, wp (to d_out) and U, V (scratch).
// ---------------------------------------------------------------------------
#define SM1_FLOATS 28096
#define SM1_BYTES  (SM1_FLOATS * 4)
#define SOFTMAX_SCALE 0.08838834764831843f   // 1/sqrt(128)

extern "C" __global__ void __launch_bounds__(256, 2)
k1_batch(const float* __restrict__ states, const float* __restrict__ policies,
         const float* __restrict__ actions, const float* __restrict__ states_people,
         const float* __restrict__ actions_people,
         const float* __restrict__ Wv, const float* __restrict__ Wvp,
         const float* __restrict__ Wf1, float* __restrict__ out) {
    extern __shared__ float sm[];
    float* s_oa  = sm;                 // 32 x 133
    float* s_oap = s_oa  + 4256;       // 32 x 133
    float* s_D   = s_oap + 4256;       // 32 x 32  (policies - actions)
    float* s_t   = s_D   + 1024;       // 32 x 128
    float* s_tp  = s_t   + 4096;       // 32 x 128
    float* s_sc  = s_tp  + 4096;       // 32 x 33
    float* s_sp  = s_sc  + 1056;       // 32 x 33
    float* s_w   = s_sp  + 1056;       // 32 x 33
    float* s_wp  = s_w   + 1056;       // 32 x 33
    float* s_A1  = s_wp  + 1056;       // 32 x 64
    float* s_B1  = s_A1  + 2048;       // 32 x 64
    float* s_C1  = s_B1  + 2048;       // 32 x 64

    const int b = blockIdx.x;
    const int t = threadIdx.x;
    const int w = t >> 5, l = t & 31, r0 = 4 * w;

    // --- load inputs ---
    {
        const float* st  = states         + (size_t)b * 32 * 96;
        const float* ac  = actions        + (size_t)b * 1024;
        const float* stp = states_people  + (size_t)b * 32 * 96;
        const float* acp = actions_people + (size_t)b * 1024;
        const float* po  = policies       + (size_t)b * 1024;
        for (int idx = t; idx < 4096; idx += 256) {
            int i = idx >> 7, c = idx & 127;
            s_oa [i * 133 + c] = (c < 96) ? st [i * 96 + c] : ac [i * 32 + c - 96];
            s_oap[i * 133 + c] = (c < 96) ? stp[i * 96 + c] : acp[i * 32 + c - 96];
        }
        for (int idx = t; idx < 1024; idx += 256) s_D[idx] = po[idx] - ac[idx];
    }
    __syncthreads();

    // --- t = oa @ M ; tp = oa @ Mp ---
    {
        ull at[4][2] = {{0,0},{0,0},{0,0},{0,0}};
        mm_acc128<128>(s_oa, 133, g_M, at, r0, l);
        store128(s_t, at, r0, l, false);
        ull atp[4][2] = {{0,0},{0,0},{0,0},{0,0}};
        mm_acc128<128>(s_oa, 133, g_Mp, atp, r0, l);
        store128(s_tp, atp, r0, l, false);
    }

    // --- scores[i,j] = t[i]·oa[j] ; sp[n,p] = tp[n]·oap[p]  (warp-local rows) ---
    {
        float a0 = 0, a1 = 0, a2 = 0, a3 = 0;
        float c0 = 0, c1 = 0, c2 = 0, c3 = 0;
        #pragma unroll 4
        for (int f = 0; f < 128; ++f) {
            float oj = s_oa [l * 133 + f];
            float pj = s_oap[l * 133 + f];
            a0 = fmaf(s_t [(r0 + 0) * 128 + f], oj, a0);
            a1 = fmaf(s_t [(r0 + 1) * 128 + f], oj, a1);
            a2 = fmaf(s_t [(r0 + 2) * 128 + f], oj, a2);
            a3 = fmaf(s_t [(r0 + 3) * 128 + f], oj, a3);
            c0 = fmaf(s_tp[(r0 + 0) * 128 + f], pj, c0);
            c1 = fmaf(s_tp[(r0 + 1) * 128 + f], pj, c1);
            c2 = fmaf(s_tp[(r0 + 2) * 128 + f], pj, c2);
            c3 = fmaf(s_tp[(r0 + 3) * 128 + f], pj, c3);
        }
        s_sc[(r0 + 0) * 33 + l] = a0;  s_sc[(r0 + 1) * 33 + l] = a1;
        s_sc[(r0 + 2) * 33 + l] = a2;  s_sc[(r0 + 3) * 33 + l] = a3;
        s_sp[(r0 + 0) * 33 + l] = c0;  s_sp[(r0 + 1) * 33 + l] = c1;
        s_sp[(r0 + 2) * 33 + l] = c2;  s_sp[(r0 + 3) * 33 + l] = c3;
    }
    __syncthreads();

    // --- column softmaxes ---
    {
        #pragma unroll
        for (int k = 0; k < 4; ++k) {
            int a = w + 8 * k;
            float v  = s_sc[l * 33 + a] * SOFTMAX_SCALE;
            float m  = warp_max(v);
            float e  = expf(v - m);
            float s  = warp_sum(e);
            float wg = e / s;
            s_w[a * 33 + l] = wg;
            out[WOFF + ((size_t)b * 32 + a) * 32 + l] = wg;
            float v2  = s_sp[l * 33 + a] * SOFTMAX_SCALE;
            float m2  = warp_max(v2);
            float e2  = expf(v2 - m2);
            float s2  = warp_sum(e2);
            s_wp[l * 33 + a] = e2 / s2;
        }
    }

    // --- va (pre-act kept in regs), vp = tanh(va_pre + D @ Wv[96:,:]) ---
    {
        ull av[4][2] = {{0,0},{0,0},{0,0},{0,0}};
        mm_acc128<128>(s_oa, 133, Wv, av, r0, l);
        store128(s_t, av, r0, l, true);                   // va -> s_t
        mm_acc128<32>(s_D, 32, Wv + 96 * 128, av, r0, l); // += delta
        store128(s_tp, av, r0, l, true);                  // vp -> s_tp
    }
    mm64<128>(s_t,  128, Wf1, s_A1, r0, l);               // A1 = va  @ W1_top
    mm64<128>(s_tp, 128, Wf1, s_B1, r0, l);               // B1 = vp  @ W1_top
    {
        ull ap[4][2] = {{0,0},{0,0},{0,0},{0,0}};
        mm_acc128<128>(s_oap, 133, Wvp, ap, r0, l);
        store128(s_t, ap, r0, l, true);                   // avp -> s_t
    }
    mm64<128>(s_t, 128, Wf1 + 128 * 64, s_C1, r0, l);     // C1 = avp @ W1_bot
    __syncthreads();

    // --- wp to global ---
    for (int idx = t; idx < 1024; idx += 256) {
        int n = idx >> 5, p = idx & 31;
        out[WPOFF + (size_t)b * 1024 + idx] = s_wp[n * 33 + p];
    }

    // --- U[a,f] = (w[a,:]·A1[:,f] + wp[a,:]·C1[:,f])/32 ; V = (B1-A1)/32 ---
    for (int idx = t; idx < 2048; idx += 256) {
        int a = idx >> 6, f = idx & 63;
        float acc = 0.f;
        #pragma unroll
        for (int j = 0; j < 32; ++j) acc = fmaf(s_w [a * 33 + j], s_A1[j * 64 + f], acc);
        #pragma unroll
        for (int p = 0; p < 32; ++p) acc = fmaf(s_wp[a * 33 + p], s_C1[p * 64 + f], acc);
        g_U[(size_t)b * 2048 + idx] = acc * 0.03125f;
        g_V[(size_t)b * 2048 + idx] = (s_B1[idx] - s_A1[idx]) * 0.03125f;
    }
}

// ---------------------------------------------------------------------------
// Kernel 2: value[b,a,i,:] = lrelu(U[b,a] + weight[b,a,i]*V[b,i]) @ W_f2
// grid 1024 (b,quarter) x 256 threads; warp = a (8 per block), lane = i.
// ---------------------------------------------------------------------------
extern "C" __global__ void __launch_bounds__(256)
k2_value(const float* __restrict__ Wf2, float* __restrict__ out) {
    __shared__ float sU [8 * 64];
    __shared__ float sV [32 * 65];
    __shared__ __align__(16) float sW2[64 * 32];
    __shared__ float sW [8 * 33];
    const int t  = threadIdx.x;
    const int b  = blockIdx.x >> 2;
    const int a0 = (blockIdx.x & 3) * 8;

    for (int idx = t; idx < 2048; idx += 256) {
        int i = idx >> 6, f = idx & 63;
        sV[i * 65 + f] = g_V[(size_t)b * 2048 + idx];
    }
    for (int idx = t; idx < 512; idx += 256)
        sU[idx] = g_U[(size_t)b * 2048 + a0 * 64 + idx];
    for (int idx = t; idx < 2048; idx += 256) sW2[idx] = Wf2[idx];
    {
        int a = t >> 5, i = t & 31;
        sW[a * 33 + i] = out[WOFF + ((size_t)b * 32 + a0 + a) * 32 + i];
    }
    __syncthreads();

    const int w = t >> 5, l = t & 31;
    const float wai = sW[w * 33 + l];
    const float* Ua = &sU[w * 64];
    ull acc[16];
    #pragma unroll
    for (int q = 0; q < 16; ++q) acc[q] = 0ull;

    #pragma unroll 8
    for (int f = 0; f < 64; ++f) {
        float h = fmaf(wai, sV[l * 65 + f], Ua[f]);
        h = fmaxf(h, 0.f) + 0.01f * fminf(h, 0.f);       // leaky_relu(0.01)
        ull hh = pk2(h);
        const ulonglong2* row = reinterpret_cast<const ulonglong2*>(&sW2[f * 32]);
        #pragma unroll
        for (int q = 0; q < 8; ++q) {
            ulonglong2 wv = row[q];
            acc[2 * q]     = ffma2(hh, wv.x, acc[2 * q]);
            acc[2 * q + 1] = ffma2(hh, wv.y, acc[2 * q + 1]);
        }
    }
    float4* op = reinterpret_cast<float4*>(out + (((size_t)b * 32 + a0 + w) * 32 + l) * 32);
    #pragma unroll
    for (int q = 0; q < 8; ++q) {
        float2 p0 = upk2(acc[2 * q]);
        float2 p1 = upk2(acc[2 * q + 1]);
        op[q] = make_float4(p0.x, p0.y, p1.x, p1.y);
    }
}

// ---------------------------------------------------------------------------
extern "C" void kernel_launch(void* const* d_in, const int* in_sizes, int n_in,
                              void* d_out, int out_size) {
    const float* states         = (const float*)d_in[0];
    const float* policies       = (const float*)d_in[1];
    const float* actions        = (const float*)d_in[2];
    const float* states_people  = (const float*)d_in[3];
    const float* actions_people = (const float*)d_in[4];
    const float* Wk  = (const float*)d_in[5];
    const float* Wq  = (const float*)d_in[6];
    const float* Wv  = (const float*)d_in[7];
    const float* Wkp = (const float*)d_in[8];
    const float* Wqp = (const float*)d_in[9];
    const float* Wvp = (const float*)d_in[10];
    const float* Wf1 = (const float*)d_in[11];
    const float* Wf2 = (const float*)d_in[12];
    float* out = (float*)d_out;

    k0_precompute<<<dim3(16, 2, 2), 256>>>(Wq, Wk, Wqp, Wkp);

    cudaFuncSetAttribute(k1_batch, cudaFuncAttributeMaxDynamicSharedMemorySize, SM1_BYTES);
    k1_batch<<<256, 256, SM1_BYTES>>>(states, policies, actions,
                                      states_people, actions_people,
                                      Wv, Wvp, Wf1, out);

    k2_value<<<1024, 256>>>(Wf2, out);
}